// round 1
// baseline (speedup 1.0000x reference)
#include <cuda_runtime.h>
#include <cuda_bf16.h>
#include <math.h>

// Problem dims (fixed by the dataset)
#define M_TOK   4096
#define D_IN    1024
#define N_EXP   16
#define P_SLOT  1024
#define H_HID   1365
#define NP      (N_EXP * P_SLOT)   // 16384

// ---------------------------------------------------------------------------
// Scratch (static __device__ globals — allocation-free per harness rules)
// ---------------------------------------------------------------------------
__device__ float g_logits[(size_t)M_TOK * NP];     // 256 MB
__device__ float g_C[(size_t)M_TOK * NP];          // 256 MB  (combine weights, row-major [m, np])
__device__ float g_Dt[(size_t)NP * M_TOK];         // 256 MB  (dispatch weights TRANSPOSED [np, m])
__device__ float g_Xs[(size_t)NP * D_IN];          // 64 MB   (slot inputs [np, d])
__device__ float g_H[(size_t)N_EXP * P_SLOT * H_HID]; // ~89 MB
__device__ float g_Ys[(size_t)NP * P_SLOT];        // 64 MB   (slot outputs [np, o])

// ---------------------------------------------------------------------------
// Generic tiled SGEMM: C = op_epi(A[M,K] * B[K,N] (+ bias))
//   BM=BN=128, BK=16, 256 threads, 8x8 per-thread tile.
//   EPI: 0 = none, 1 = +bias (per output column), 2 = +bias then ReLU
//   Batched via blockIdx.z with element strides.
// ---------------------------------------------------------------------------
template <int EPI>
__global__ __launch_bounds__(256)
void sgemm128(const float* __restrict__ A, const float* __restrict__ B,
              const float* __restrict__ bias, float* __restrict__ Cout,
              int M, int N, int K,
              long strideA, long strideB, long strideBias, long strideC)
{
    constexpr int BM = 128, BN = 128, BK = 16;
    __shared__ float As[BK][BM + 4];  // +4 pad: keeps 16B alignment, reduces ST conflicts
    __shared__ float Bs[BK][BN];

    const int tid = threadIdx.x;
    const int z   = blockIdx.z;
    A    += (long)z * strideA;
    B    += (long)z * strideB;
    Cout += (long)z * strideC;
    const float* biasp = (EPI >= 1) ? (bias + (long)z * strideBias) : nullptr;

    const int cRow = blockIdx.y * BM;
    const int cCol = blockIdx.x * BN;

    const int threadRow = tid / 16;   // 0..15
    const int threadCol = tid % 16;   // 0..15

    float acc[8][8] = {};
    float ar[8], br[8];

    for (int k0 = 0; k0 < K; k0 += BK) {
        // Load A tile (BM x BK), store transposed into As[k][row]
        #pragma unroll
        for (int j = 0; j < 8; j++) {
            int idx = tid + j * 256;            // 0..2047
            int col = idx % BK;                 // k within tile
            int row = idx / BK;                 // 0..127
            int gr = cRow + row, gc = k0 + col;
            As[col][row] = (gr < M && gc < K) ? A[(long)gr * K + gc] : 0.0f;
        }
        // Load B tile (BK x BN)
        #pragma unroll
        for (int j = 0; j < 8; j++) {
            int idx = tid + j * 256;
            int col = idx % BN;
            int row = idx / BN;                 // 0..15
            int gr = k0 + row, gc = cCol + col;
            Bs[row][col] = (gr < K && gc < N) ? B[(long)gr * N + gc] : 0.0f;
        }
        __syncthreads();

        #pragma unroll
        for (int k = 0; k < BK; k++) {
            #pragma unroll
            for (int i = 0; i < 8; i++) ar[i] = As[k][threadRow * 8 + i];
            #pragma unroll
            for (int j = 0; j < 8; j++) br[j] = Bs[k][threadCol * 8 + j];
            #pragma unroll
            for (int i = 0; i < 8; i++)
                #pragma unroll
                for (int j = 0; j < 8; j++)
                    acc[i][j] = fmaf(ar[i], br[j], acc[i][j]);
        }
        __syncthreads();
    }

    // Epilogue
    #pragma unroll
    for (int i = 0; i < 8; i++) {
        int gr = cRow + threadRow * 8 + i;
        if (gr >= M) continue;
        #pragma unroll
        for (int j = 0; j < 8; j++) {
            int gc = cCol + threadCol * 8 + j;
            if (gc >= N) continue;
            float v = acc[i][j];
            if (EPI >= 1) v += biasp[gc];
            if (EPI == 2) v = fmaxf(v, 0.0f);
            Cout[(long)gr * N + gc] = v;
        }
    }
}

// ---------------------------------------------------------------------------
// Softmax kernel: one block per token m.
//  - C[m, np]  = softmax over all 16384 (n,p)
//  - Dt[np, m] = softmax over n (16 experts) for each p
// ---------------------------------------------------------------------------
__global__ __launch_bounds__(256)
void softmax_kernel(const float* __restrict__ logits,
                    float* __restrict__ Cmat,
                    float* __restrict__ Dt)
{
    const int m = blockIdx.x;
    const float* row = logits + (size_t)m * NP;
    const int tid = threadIdx.x;
    __shared__ float red[256];

    // --- row max over 16384 ---
    float mx = -INFINITY;
    for (int i = tid; i < NP; i += 256) mx = fmaxf(mx, row[i]);
    red[tid] = mx; __syncthreads();
    for (int s = 128; s > 0; s >>= 1) {
        if (tid < s) red[tid] = fmaxf(red[tid], red[tid + s]);
        __syncthreads();
    }
    mx = red[0]; __syncthreads();

    // --- row sum of exp ---
    float sum = 0.0f;
    for (int i = tid; i < NP; i += 256) sum += __expf(row[i] - mx);
    red[tid] = sum; __syncthreads();
    for (int s = 128; s > 0; s >>= 1) {
        if (tid < s) red[tid] += red[tid + s];
        __syncthreads();
    }
    sum = red[0];
    const float inv = 1.0f / sum;

    // --- write C (coalesced) ---
    float* crow = Cmat + (size_t)m * NP;
    for (int i = tid; i < NP; i += 256) crow[i] = __expf(row[i] - mx) * inv;

    // --- D: softmax over 16 experts per slot p, write transposed ---
    for (int p = tid; p < P_SLOT; p += 256) {
        float l[N_EXP];
        float mn = -INFINITY;
        #pragma unroll
        for (int n = 0; n < N_EXP; n++) {
            l[n] = row[n * P_SLOT + p];
            mn = fmaxf(mn, l[n]);
        }
        float s2 = 0.0f;
        #pragma unroll
        for (int n = 0; n < N_EXP; n++) {
            l[n] = __expf(l[n] - mn);
            s2 += l[n];
        }
        const float inv2 = 1.0f / s2;
        #pragma unroll
        for (int n = 0; n < N_EXP; n++)
            Dt[(size_t)(n * P_SLOT + p) * M_TOK + m] = l[n] * inv2;
    }
}

// ---------------------------------------------------------------------------
// Launch
// ---------------------------------------------------------------------------
extern "C" void kernel_launch(void* const* d_in, const int* in_sizes, int n_in,
                              void* d_out, int out_size)
{
    const float* x   = (const float*)d_in[0];   // [4096, 1024]
    const float* phi = (const float*)d_in[1];   // [1024, 16, 1024] -> [1024, 16384]
    const float* W1  = (const float*)d_in[2];   // [16, 1024, 1365]
    const float* b1  = (const float*)d_in[3];   // [16, 1365]
    const float* W2  = (const float*)d_in[4];   // [16, 1365, 1024]
    const float* b2  = (const float*)d_in[5];   // [16, 1024]
    float* out = (float*)d_out;                 // [4096, 1024]

    float *logits, *Cm, *Dt, *Xs, *H, *Ys;
    cudaGetSymbolAddress((void**)&logits, g_logits);
    cudaGetSymbolAddress((void**)&Cm,     g_C);
    cudaGetSymbolAddress((void**)&Dt,     g_Dt);
    cudaGetSymbolAddress((void**)&Xs,     g_Xs);
    cudaGetSymbolAddress((void**)&H,      g_H);
    cudaGetSymbolAddress((void**)&Ys,     g_Ys);

    dim3 blk(256);

    // 1) logits[m, np] = x[m,d] @ phi[d, np]    (4096 x 16384 x 1024)
    sgemm128<0><<<dim3(NP / 128, M_TOK / 128), blk>>>(
        x, phi, nullptr, logits, M_TOK, NP, D_IN, 0, 0, 0, 0);

    // 2) softmaxes -> C [m,np], Dt [np,m]
    softmax_kernel<<<M_TOK, 256>>>(logits, Cm, Dt);

    // 3) Xs[np, d] = Dt[np, m] @ x[m, d]        (16384 x 1024 x 4096)
    sgemm128<0><<<dim3(D_IN / 128, NP / 128), blk>>>(
        Dt, x, nullptr, Xs, NP, D_IN, M_TOK, 0, 0, 0, 0);

    // 4) H[n] = relu(Xs[n] @ W1[n] + b1[n])     batched: 1024 x 1365 x 1024
    sgemm128<2><<<dim3((H_HID + 127) / 128, P_SLOT / 128, N_EXP), blk>>>(
        Xs, W1, b1, H, P_SLOT, H_HID, D_IN,
        (long)P_SLOT * D_IN, (long)D_IN * H_HID, (long)H_HID, (long)P_SLOT * H_HID);

    // 5) Ys[n] = H[n] @ W2[n] + b2[n]           batched: 1024 x 1024 x 1365
    sgemm128<1><<<dim3(P_SLOT / 128, P_SLOT / 128, N_EXP), blk>>>(
        H, W2, b2, Ys, P_SLOT, P_SLOT, H_HID,
        (long)P_SLOT * H_HID, (long)H_HID * P_SLOT, (long)P_SLOT, (long)P_SLOT * P_SLOT);

    // 6) Y[m, o] = C[m, np] @ Ys[np, o]         (4096 x 1024 x 16384)
    sgemm128<0><<<dim3(P_SLOT / 128, M_TOK / 128), blk>>>(
        Cm, Ys, nullptr, out, M_TOK, P_SLOT, NP, 0, 0, 0, 0);

    (void)in_sizes; (void)n_in; (void)out_size;
}

// round 3
// speedup vs baseline: 2.8746x; 2.8746x over previous
#include <cuda_runtime.h>
#include <cuda_bf16.h>
#include <math.h>
#include <stdint.h>

// ---------------- problem dims ----------------
#define M_TOK 4096
#define D_IN  1024
#define N_EXP 16
#define P_SLOT 1024
#define H_HID 1365
#define H_PAD 1408
#define NP    16384

#define KP1 (3*D_IN)    // 3072   K' for logits / MLP1
#define KP3 (3*M_TOK)   // 12288  K' for dispatch
#define KPH (3*H_PAD)   // 4224   K' for MLP2
#define KP6 (3*NP)      // 49152  K' for combine

// ---------------- scratch ----------------
__device__ float        g_logits[(size_t)M_TOK*NP];
__device__ float        g_D     [(size_t)M_TOK*NP];
__device__ __nv_bfloat16 g_Cext [(size_t)M_TOK*KP6];
__device__ __nv_bfloat16 g_Dtext[(size_t)NP*KP3];
__device__ __nv_bfloat16 g_xext [(size_t)M_TOK*KP1];
__device__ __nv_bfloat16 g_xT   [(size_t)D_IN*KP3];
__device__ __nv_bfloat16 g_phiT [(size_t)NP*KP1];
__device__ __nv_bfloat16 g_W1T  [(size_t)N_EXP*H_HID*KP1];
__device__ __nv_bfloat16 g_W2T  [(size_t)N_EXP*P_SLOT*KPH];
__device__ __nv_bfloat16 g_Xsext[(size_t)NP*KP1];
__device__ __nv_bfloat16 g_Hext [(size_t)N_EXP*P_SLOT*KPH];
__device__ __nv_bfloat16 g_YsT  [(size_t)P_SLOT*KP6];

// ---------------- helpers ----------------
__device__ __forceinline__ uint32_t smem_u32(const void* p) {
    return (uint32_t)__cvta_generic_to_shared(p);
}
#define SWZ(x) ((x) ^ (((x) >> 3) & 0x70))

__device__ __forceinline__ void split_bf16(float v, __nv_bfloat16& hi, __nv_bfloat16& lo) {
    hi = __float2bfloat16(v);
    lo = __float2bfloat16(v - __bfloat162float(hi));
}

__device__ __forceinline__ void ldsm_x4(uint32_t* r, uint32_t addr) {
    asm volatile("ldmatrix.sync.aligned.m8n8.x4.shared.b16 {%0,%1,%2,%3}, [%4];"
                 : "=r"(r[0]), "=r"(r[1]), "=r"(r[2]), "=r"(r[3]) : "r"(addr));
}
__device__ __forceinline__ void mma16816(float* c, const uint32_t* a, const uint32_t* b) {
    asm volatile("mma.sync.aligned.m16n8k16.row.col.f32.bf16.bf16.f32 "
        "{%0,%1,%2,%3}, {%4,%5,%6,%7}, {%8,%9}, {%0,%1,%2,%3};"
        : "+f"(c[0]), "+f"(c[1]), "+f"(c[2]), "+f"(c[3])
        : "r"(a[0]), "r"(a[1]), "r"(a[2]), "r"(a[3]), "r"(b[0]), "r"(b[1]));
}
__device__ __forceinline__ void cp16(uint32_t dst, const void* src, int srcsize) {
    asm volatile("cp.async.cg.shared.global [%0], [%1], 16, %2;"
                 :: "r"(dst), "l"(src), "r"(srcsize) : "memory");
}
#define CP_COMMIT() asm volatile("cp.async.commit_group;" ::: "memory")
#define CP_WAIT(n)  asm volatile("cp.async.wait_group %0;" :: "n"(n) : "memory")

// smem: 3 stages x (A 16KB + B 16KB)
#define STG        3
#define STG_BYTES  32768
#define SMEM_GEMM  (STG * STG_BYTES)

// ---------------------------------------------------------------------------
// HMMA GEMM: D[m0..+128, n0..+128] = A[M,K'] * B[N,K']^T  (both K-major bf16)
// EPI: 0 = fp32 row-major (ldOut)
//      1 = bf16 EXT-A [hi|lo|hi] rows (segK)
//      2 = bf16 EXT-A + bias + relu + zero-pad cols [outN, segK)
//      3 = bf16 EXT-B [hi|hi|lo] TRANSPOSED (out row = gc, k = z*gridX*128 + gm) + bias
// ---------------------------------------------------------------------------
template<int EPI, bool BCHECK>
__global__ __launch_bounds__(256, 2)
void gemm_mma(const __nv_bfloat16* __restrict__ A, const __nv_bfloat16* __restrict__ B,
              const float* __restrict__ bias, void* __restrict__ outp,
              int Kp, int Nrows, int ldA, int ldB,
              long sA, long sB, long sBias, long outBatch,
              int ldOut, int segK, int outN)
{
    extern __shared__ char smraw[];
    const uint32_t smb = smem_u32(smraw);
    const int tid = threadIdx.x, wid = tid >> 5, lane = tid & 31;
    const int z  = blockIdx.z;
    const int m0 = blockIdx.x * 128, n0 = blockIdx.y * 128;
    A += (long)z * sA;
    B += (long)z * sB;
    const float* biasp = bias ? (bias + (long)z * sBias) : bias;

    const int nCh = Kp >> 6;          // K chunks of 64 bf16 (128B)
    const int lrow = tid >> 3;        // 0..31
    const int lj   = tid & 7;         // 16B lane within 128B row

    auto issue = [&](int c) {
        const int st = c % STG;
        const uint32_t smA = smb + st * STG_BYTES;
        const uint32_t smB = smA + 16384;
        const long kb = (long)c * 64 + lj * 8;   // bf16 element offset
        #pragma unroll
        for (int i = 0; i < 4; ++i) {
            int r = lrow + i * 32;
            cp16(smA + SWZ(r * 128 + lj * 16), A + (long)(m0 + r) * ldA + kb, 16);
        }
        #pragma unroll
        for (int i = 0; i < 4; ++i) {
            int r = lrow + i * 32;
            int ok = (!BCHECK) || (n0 + r) < Nrows;
            const __nv_bfloat16* src = B + (long)(ok ? (n0 + r) : 0) * ldB + kb;
            cp16(smB + SWZ(r * 128 + lj * 16), src, ok ? 16 : 0);
        }
        CP_COMMIT();
    };

    float acc[4][4][4] = {};                 // [mb][nb][c0..c3]
    const int wm = (wid >> 2) * 64;          // warp m offset (0/64)
    const int wn = (wid & 3) * 32;           // warp n offset (0/32/64/96)

    issue(0);
    if (nCh > 1) issue(1);

    for (int c = 0; c < nCh; ++c) {
        if (c + 1 < nCh) { CP_WAIT(1); } else { CP_WAIT(0); }
        __syncthreads();
        if (c + 2 < nCh) issue(c + 2);

        const uint32_t smA = smb + (c % STG) * STG_BYTES;
        const uint32_t smB = smA + 16384;

        #pragma unroll
        for (int ks = 0; ks < 4; ++ks) {
            const int kb = ks * 32;          // byte offset of k16 within 128B row
            uint32_t af[4][4], bf[4][2];
            #pragma unroll
            for (int mb = 0; mb < 4; ++mb) {
                int row = wm + mb * 16 + (lane & 15);
                ldsm_x4(af[mb], smA + SWZ(row * 128 + kb + ((lane >> 4) << 4)));
            }
            #pragma unroll
            for (int npair = 0; npair < 2; ++npair) {
                int row = wn + npair * 16 + (lane & 7) + ((lane >> 4) << 3);
                uint32_t r4[4];
                ldsm_x4(r4, smB + SWZ(row * 128 + kb + (((lane >> 3) & 1) << 4)));
                bf[npair*2  ][0] = r4[0]; bf[npair*2  ][1] = r4[1];
                bf[npair*2+1][0] = r4[2]; bf[npair*2+1][1] = r4[3];
            }
            #pragma unroll
            for (int mb = 0; mb < 4; ++mb)
                #pragma unroll
                for (int nb = 0; nb < 4; ++nb)
                    mma16816(acc[mb][nb], af[mb], bf[nb]);
        }
    }

    // ---------------- epilogue (register fragments -> global) ----------------
    const int erow = lane >> 2;
    const int ecol = (lane & 3) * 2;
    #pragma unroll
    for (int mb = 0; mb < 4; ++mb) {
        #pragma unroll
        for (int nb = 0; nb < 4; ++nb) {
            float* cc = acc[mb][nb];
            const int gm = m0 + wm + mb * 16 + erow;
            const int gc = n0 + wn + nb * 8 + ecol;
            if (EPI == 0) {
                *(float2*)((float*)outp + (long)gm * ldOut + gc)       = make_float2(cc[0], cc[1]);
                *(float2*)((float*)outp + (long)(gm + 8) * ldOut + gc) = make_float2(cc[2], cc[3]);
            } else if (EPI == 3) {
                const long kBase = (long)z * ((long)gridDim.x * 128);
                #pragma unroll
                for (int h = 0; h < 2; ++h)
                    #pragma unroll
                    for (int q = 0; q < 2; ++q) {
                        int gmm = gm + h * 8, gcc = gc + q;
                        float v = cc[h * 2 + q] + biasp[gcc];
                        __nv_bfloat16 hi, lo; split_bf16(v, hi, lo);
                        __nv_bfloat16* o = (__nv_bfloat16*)outp + (long)gcc * (3L * segK) + kBase + gmm;
                        o[0] = hi; o[segK] = hi; o[2L * segK] = lo;
                    }
            } else {
                #pragma unroll
                for (int h = 0; h < 2; ++h)
                    #pragma unroll
                    for (int q = 0; q < 2; ++q) {
                        int gmm = gm + h * 8, gcc = gc + q;
                        float v = cc[h * 2 + q];
                        if (EPI == 2) v = (gcc < outN) ? fmaxf(v + biasp[gcc], 0.0f) : 0.0f;
                        __nv_bfloat16 hi, lo; split_bf16(v, hi, lo);
                        __nv_bfloat16* o = (__nv_bfloat16*)outp + (long)z * outBatch
                                         + (long)gmm * (3L * segK) + gcc;
                        o[0] = hi; o[segK] = lo; o[2L * segK] = hi;
                    }
            }
        }
    }
}

// ---------------------------------------------------------------------------
// elementwise convert: fp32 [R,C] -> EXT-A bf16 [R, 3C]  (hi | lo | hi)
// ---------------------------------------------------------------------------
__global__ __launch_bounds__(256) void convert_A_ext(const float* __restrict__ in,
                                                     __nv_bfloat16* __restrict__ out,
                                                     int R, int C)
{
    long total = (long)R * C;
    for (long idx = blockIdx.x * 256L + threadIdx.x; idx < total; idx += (long)gridDim.x * 256) {
        int r = (int)(idx / C), c = (int)(idx % C);
        __nv_bfloat16 hi, lo; split_bf16(in[idx], hi, lo);
        __nv_bfloat16* o = out + (long)r * (3L * C) + c;
        o[0] = hi; o[C] = lo; o[2L * C] = hi;
    }
}

// ---------------------------------------------------------------------------
// transpose+convert: fp32 in[R,Cc] -> bf16 out[Cc, 3*segK], out[c][k]=in[k][c] (k<R else 0)
// BL=true  -> EXT-B (hi|hi|lo);  BL=false -> EXT-A (hi|lo|hi)
// ---------------------------------------------------------------------------
template<bool BL>
__global__ __launch_bounds__(256) void transpose_ext(const float* __restrict__ in,
                                                     __nv_bfloat16* __restrict__ out,
                                                     int R, int Cc, int segK,
                                                     long inBatch, long outBatch)
{
    __shared__ float t[32][33];
    const int z = blockIdx.z;
    in  += (long)z * inBatch;
    out += (long)z * outBatch;
    const int c0 = blockIdx.x * 32, k0 = blockIdx.y * 32;
    const int tx = threadIdx.x, ty = threadIdx.y;   // 32 x 8

    #pragma unroll
    for (int i = 0; i < 4; ++i) {
        int k = k0 + ty + i * 8, c = c0 + tx;
        float v = 0.0f;
        if (k < R && c < Cc) v = in[(long)k * Cc + c];
        t[ty + i * 8][tx] = v;
    }
    __syncthreads();
    #pragma unroll
    for (int i = 0; i < 4; ++i) {
        int c = c0 + ty + i * 8, k = k0 + tx;
        if (c < Cc && k < segK) {
            __nv_bfloat16 hi, lo; split_bf16(t[tx][ty + i * 8], hi, lo);
            __nv_bfloat16* o = out + (long)c * (3L * segK) + k;
            if (BL) { o[0] = hi; o[segK] = hi; o[2L * segK] = lo; }
            else    { o[0] = hi; o[segK] = lo; o[2L * segK] = hi; }
        }
    }
}

// ---------------------------------------------------------------------------
// softmax: per token m. C_ext [m, 3*NP] (hi|lo|hi), D fp32 [m, NP]
// ---------------------------------------------------------------------------
__global__ __launch_bounds__(256) void softmax_kernel(const float* __restrict__ logits,
                                                      __nv_bfloat16* __restrict__ Cext,
                                                      float* __restrict__ D)
{
    extern __shared__ float row[];               // 16384 floats
    __shared__ float red[256];
    const int m = blockIdx.x, tid = threadIdx.x;
    const float* lrow = logits + (size_t)m * NP;

    float mx = -INFINITY;
    for (int i = tid; i < NP; i += 256) { float v = lrow[i]; row[i] = v; mx = fmaxf(mx, v); }
    red[tid] = mx; __syncthreads();
    for (int s = 128; s > 0; s >>= 1) { if (tid < s) red[tid] = fmaxf(red[tid], red[tid + s]); __syncthreads(); }
    mx = red[0]; __syncthreads();

    float sum = 0.0f;
    for (int i = tid; i < NP; i += 256) sum += expf(row[i] - mx);
    red[tid] = sum; __syncthreads();
    for (int s = 128; s > 0; s >>= 1) { if (tid < s) red[tid] += red[tid + s]; __syncthreads(); }
    const float inv = 1.0f / red[0];

    __nv_bfloat16* crow = Cext + (size_t)m * KP6;
    for (int i = tid; i < NP; i += 256) {
        float c = expf(row[i] - mx) * inv;
        __nv_bfloat16 hi, lo; split_bf16(c, hi, lo);
        crow[i] = hi; crow[NP + i] = lo; crow[2 * NP + i] = hi;
    }

    float* drow = D + (size_t)m * NP;
    for (int p = tid; p < P_SLOT; p += 256) {
        float l[N_EXP], mn = -INFINITY;
        #pragma unroll
        for (int n = 0; n < N_EXP; n++) { l[n] = row[n * P_SLOT + p]; mn = fmaxf(mn, l[n]); }
        float s2 = 0.0f;
        #pragma unroll
        for (int n = 0; n < N_EXP; n++) { l[n] = expf(l[n] - mn); s2 += l[n]; }
        const float inv2 = 1.0f / s2;
        #pragma unroll
        for (int n = 0; n < N_EXP; n++) drow[n * P_SLOT + p] = l[n] * inv2;
    }
}

// ---------------------------------------------------------------------------
extern "C" void kernel_launch(void* const* d_in, const int* in_sizes, int n_in,
                              void* d_out, int out_size)
{
    const float* x   = (const float*)d_in[0];
    const float* phi = (const float*)d_in[1];
    const float* W1  = (const float*)d_in[2];
    const float* b1  = (const float*)d_in[3];
    const float* W2  = (const float*)d_in[4];
    const float* b2  = (const float*)d_in[5];
    float* out = (float*)d_out;

    float *logits, *D;
    __nv_bfloat16 *Cext, *Dtext, *xext, *xT, *phiT, *W1T, *W2T, *Xsext, *Hext, *YsT;
    cudaGetSymbolAddress((void**)&logits, g_logits);
    cudaGetSymbolAddress((void**)&D,      g_D);
    cudaGetSymbolAddress((void**)&Cext,   g_Cext);
    cudaGetSymbolAddress((void**)&Dtext,  g_Dtext);
    cudaGetSymbolAddress((void**)&xext,   g_xext);
    cudaGetSymbolAddress((void**)&xT,     g_xT);
    cudaGetSymbolAddress((void**)&phiT,   g_phiT);
    cudaGetSymbolAddress((void**)&W1T,    g_W1T);
    cudaGetSymbolAddress((void**)&W2T,    g_W2T);
    cudaGetSymbolAddress((void**)&Xsext,  g_Xsext);
    cudaGetSymbolAddress((void**)&Hext,   g_Hext);
    cudaGetSymbolAddress((void**)&YsT,    g_YsT);

    cudaFuncSetAttribute(gemm_mma<0,false>, cudaFuncAttributeMaxDynamicSharedMemorySize, SMEM_GEMM);
    cudaFuncSetAttribute(gemm_mma<1,false>, cudaFuncAttributeMaxDynamicSharedMemorySize, SMEM_GEMM);
    cudaFuncSetAttribute(gemm_mma<2,true>,  cudaFuncAttributeMaxDynamicSharedMemorySize, SMEM_GEMM);
    cudaFuncSetAttribute(gemm_mma<3,false>, cudaFuncAttributeMaxDynamicSharedMemorySize, SMEM_GEMM);
    cudaFuncSetAttribute(softmax_kernel,    cudaFuncAttributeMaxDynamicSharedMemorySize, NP * 4);

    dim3 t256(256), t32x8(32, 8);

    // operand prep
    convert_A_ext<<<4096, t256>>>(x, xext, M_TOK, D_IN);
    transpose_ext<true><<<dim3(NP/32, D_IN/32, 1),    t32x8>>>(phi, phiT, D_IN, NP, D_IN, 0, 0);
    transpose_ext<true><<<dim3(D_IN/32, M_TOK/32, 1), t32x8>>>(x, xT, M_TOK, D_IN, M_TOK, 0, 0);
    transpose_ext<true><<<dim3(43, D_IN/32, N_EXP),   t32x8>>>(W1, W1T, D_IN, H_HID, D_IN,
                                                      (long)D_IN*H_HID, (long)H_HID*KP1);
    transpose_ext<true><<<dim3(P_SLOT/32, 44, N_EXP), t32x8>>>(W2, W2T, H_HID, P_SLOT, H_PAD,
                                                      (long)H_HID*P_SLOT, (long)P_SLOT*KPH);

    // 1) logits = x @ phi   (M=4096, N=16384, K'=3072)
    gemm_mma<0,false><<<dim3(M_TOK/128, NP/128), t256, SMEM_GEMM>>>(
        xext, phiT, nullptr, logits, KP1, NP, KP1, KP1, 0,0,0,0, NP, 0, 0);

    // 2) softmaxes
    softmax_kernel<<<M_TOK, t256, NP*4>>>(logits, Cext, D);

    // 3) D -> Dt_ext (EXT-A, transposed)
    transpose_ext<false><<<dim3(NP/32, M_TOK/32, 1), t32x8>>>(D, Dtext, M_TOK, NP, M_TOK, 0, 0);

    // 4) Xs = Dt @ x^T   (M=16384, N=1024, K'=12288) -> EXT-A segK=1024
    gemm_mma<1,false><<<dim3(NP/128, D_IN/128), t256, SMEM_GEMM>>>(
        Dtext, xT, nullptr, Xsext, KP3, D_IN, KP3, KP3, 0,0,0,0, 0, D_IN, 0);

    // 5) H = relu(Xs @ W1 + b1)  per expert (M=1024, N=1365, K'=3072) -> EXT-A segK=1408
    gemm_mma<2,true><<<dim3(P_SLOT/128, 11, N_EXP), t256, SMEM_GEMM>>>(
        Xsext, W1T, b1, Hext, KP1, H_HID, KP1, KP1,
        (long)P_SLOT*KP1, (long)H_HID*KP1, H_HID, (long)P_SLOT*KPH, 0, H_PAD, H_HID);

    // 6) Ys = H @ W2 + b2  per expert (M=1024, N=1024, K'=4224) -> EXT-B transposed segK=16384
    gemm_mma<3,false><<<dim3(P_SLOT/128, P_SLOT/128, N_EXP), t256, SMEM_GEMM>>>(
        Hext, W2T, b2, YsT, KPH, P_SLOT, KPH, KPH,
        (long)P_SLOT*KPH, (long)P_SLOT*KPH, P_SLOT, 0, 0, NP, 0);

    // 7) Y = C @ Ys^T  (M=4096, N=1024, K'=49152)
    gemm_mma<0,false><<<dim3(M_TOK/128, D_IN/128), t256, SMEM_GEMM>>>(
        Cext, YsT, nullptr, out, KP6, D_IN, KP6, KP6, 0,0,0,0, D_IN, 0, 0);

    (void)in_sizes; (void)n_in; (void)out_size;
}

// round 5
// speedup vs baseline: 7.2052x; 2.5065x over previous
#include <cuda_runtime.h>
#include <cuda_fp16.h>
#include <math.h>
#include <stdint.h>

// ---------------- problem dims ----------------
#define M_TOK 4096
#define D_IN  1024
#define N_EXP 16
#define P_SLOT 1024
#define H_HID 1365
#define H_PAD 1408
#define NP    16384

// ---------------- scratch ----------------
// A-operands: [hi|lo] 2 segments along K (fp16).  B-operands: plain fp16 (hi only).
__device__ float  g_logits[(size_t)M_TOK*NP];
__device__ float  g_D     [(size_t)M_TOK*NP];
__device__ __half g_Cext [(size_t)M_TOK*2*NP];
__device__ __half g_Dtext[(size_t)NP*2*M_TOK];
__device__ __half g_xext [(size_t)M_TOK*2*D_IN];
__device__ __half g_xT   [(size_t)D_IN*M_TOK];
__device__ __half g_phiT [(size_t)NP*D_IN];
__device__ __half g_W1T  [(size_t)N_EXP*H_HID*D_IN];
__device__ __half g_W2T  [(size_t)N_EXP*P_SLOT*H_PAD];
__device__ __half g_Xsext[(size_t)NP*2*D_IN];
__device__ __half g_Hext [(size_t)N_EXP*P_SLOT*2*H_PAD];
__device__ __half g_YsT  [(size_t)P_SLOT*NP];

// ---------------- helpers ----------------
__device__ __forceinline__ uint32_t smem_u32(const void* p) {
    return (uint32_t)__cvta_generic_to_shared(p);
}
#define SWZ(x) ((x) ^ (((x) >> 3) & 0x70))

__device__ __forceinline__ void split_f16(float v, __half& hi, __half& lo) {
    hi = __float2half(v);
    lo = __float2half(v - __half2float(hi));
}

__device__ __forceinline__ void ldsm_x4(uint32_t* r, uint32_t addr) {
    asm volatile("ldmatrix.sync.aligned.m8n8.x4.shared.b16 {%0,%1,%2,%3}, [%4];"
                 : "=r"(r[0]), "=r"(r[1]), "=r"(r[2]), "=r"(r[3]) : "r"(addr));
}
__device__ __forceinline__ void mma16816(float* c, const uint32_t* a, const uint32_t* b) {
    asm volatile("mma.sync.aligned.m16n8k16.row.col.f32.f16.f16.f32 "
        "{%0,%1,%2,%3}, {%4,%5,%6,%7}, {%8,%9}, {%0,%1,%2,%3};"
        : "+f"(c[0]), "+f"(c[1]), "+f"(c[2]), "+f"(c[3])
        : "r"(a[0]), "r"(a[1]), "r"(a[2]), "r"(a[3]), "r"(b[0]), "r"(b[1]));
}
__device__ __forceinline__ void cp16(uint32_t dst, const void* src, int srcsize) {
    asm volatile("cp.async.cg.shared.global [%0], [%1], 16, %2;"
                 :: "r"(dst), "l"(src), "r"(srcsize) : "memory");
}
#define CP_COMMIT() asm volatile("cp.async.commit_group;" ::: "memory")
#define CP_WAIT(n)  asm volatile("cp.async.wait_group %0;" :: "n"(n) : "memory")

// smem: 2 stages x (Ahi 16KB + Alo 16KB + B 16KB)
#define STG_BYTES  49152
#define SMEM_GEMM  (2 * STG_BYTES)

// ---------------------------------------------------------------------------
// HMMA GEMM with 2-term fp16 split:
//   D[128,128] += (A_hi + A_lo)[M, K] * B_hi[N, K]^T
// A rows: [hi(0..K-1) | lo(K..2K-1)], ldA = 2K.  B rows: plain fp16, ldB = K.
// CTA 128x128, 4 warps each 64x64.
// EPI: 0 = fp32 row-major (ldOut)
//      1 = fp16 [hi|lo] rows (segK)
//      2 = fp16 [hi|lo] + bias + relu + zero-pad cols [outN, segK)
//      3 = fp16 hi-only TRANSPOSED (row = gc, k = z*gridX*128 + gm) + bias; row len segK
// ---------------------------------------------------------------------------
template<int EPI, bool BCHECK>
__global__ __launch_bounds__(128, 2)
void gemm_mma(const __half* __restrict__ A, const __half* __restrict__ B,
              const float* __restrict__ bias, void* __restrict__ outp,
              int K, int Nrows, int ldA, int ldB,
              long sA, long sB, long sBias, long outBatch,
              int ldOut, int segK, int outN)
{
    extern __shared__ char smraw[];
    const uint32_t smb = smem_u32(smraw);
    const int tid = threadIdx.x, wid = tid >> 5, lane = tid & 31;
    const int z  = blockIdx.z;
    const int m0 = blockIdx.x * 128, n0 = blockIdx.y * 128;
    A += (long)z * sA;
    B += (long)z * sB;
    const float* biasp = bias ? (bias + (long)z * sBias) : bias;

    const int nCh = K >> 6;           // K chunks of 64 fp16 (128B)
    const int lrow = tid >> 3;        // 0..15
    const int lj   = tid & 7;         // 16B lane within 128B row

    auto issue = [&](int c) {
        const uint32_t smAhi = smb + (c & 1) * STG_BYTES;
        const uint32_t smAlo = smAhi + 16384;
        const uint32_t smB   = smAhi + 32768;
        const long kb = (long)c * 64 + lj * 8;   // fp16 element offset
        #pragma unroll
        for (int i = 0; i < 8; ++i) {
            int r = lrow + i * 16;
            const __half* src = A + (long)(m0 + r) * ldA + kb;
            cp16(smAhi + SWZ(r * 128 + lj * 16), src, 16);
            cp16(smAlo + SWZ(r * 128 + lj * 16), src + K, 16);
        }
        #pragma unroll
        for (int i = 0; i < 8; ++i) {
            int r = lrow + i * 16;
            int ok = (!BCHECK) || (n0 + r) < Nrows;
            const __half* src = B + (long)(ok ? (n0 + r) : 0) * ldB + kb;
            cp16(smB + SWZ(r * 128 + lj * 16), src, ok ? 16 : 0);
        }
        CP_COMMIT();
    };

    float acc[4][8][4] = {};                 // [mb][nb][c0..c3]
    const int wm = (wid >> 1) * 64;          // warp m offset (0/64)
    const int wn = (wid & 1) * 64;           // warp n offset (0/64)

    issue(0);

    for (int c = 0; c < nCh; ++c) {
        if (c + 1 < nCh) { issue(c + 1); CP_WAIT(1); } else { CP_WAIT(0); }
        __syncthreads();

        const uint32_t smAhi = smb + (c & 1) * STG_BYTES;
        const uint32_t smAlo = smAhi + 16384;
        const uint32_t smB   = smAhi + 32768;

        #pragma unroll
        for (int ks = 0; ks < 4; ++ks) {
            const int kb = ks * 32;          // byte offset of k16 within 128B row
            uint32_t ah[4][4], al[4][4], bf[8][2];
            #pragma unroll
            for (int mb = 0; mb < 4; ++mb) {
                int row = wm + mb * 16 + (lane & 15);
                uint32_t off = SWZ(row * 128 + kb + ((lane >> 4) << 4));
                ldsm_x4(ah[mb], smAhi + off);
                ldsm_x4(al[mb], smAlo + off);
            }
            #pragma unroll
            for (int npair = 0; npair < 4; ++npair) {
                int row = wn + npair * 16 + (lane & 7) + ((lane >> 4) << 3);
                uint32_t r4[4];
                ldsm_x4(r4, smB + SWZ(row * 128 + kb + (((lane >> 3) & 1) << 4)));
                bf[npair*2  ][0] = r4[0]; bf[npair*2  ][1] = r4[1];
                bf[npair*2+1][0] = r4[2]; bf[npair*2+1][1] = r4[3];
            }
            #pragma unroll
            for (int mb = 0; mb < 4; ++mb)
                #pragma unroll
                for (int nb = 0; nb < 8; ++nb) {
                    mma16816(acc[mb][nb], ah[mb], bf[nb]);
                    mma16816(acc[mb][nb], al[mb], bf[nb]);
                }
        }
        __syncthreads();
    }

    // ---------------- epilogue (register fragments -> global) ----------------
    const int erow = lane >> 2;
    const int ecol = (lane & 3) * 2;
    #pragma unroll
    for (int mb = 0; mb < 4; ++mb) {
        #pragma unroll
        for (int nb = 0; nb < 8; ++nb) {
            float* cc = acc[mb][nb];
            const int gm = m0 + wm + mb * 16 + erow;
            const int gc = n0 + wn + nb * 8 + ecol;
            if (EPI == 0) {
                *(float2*)((float*)outp + (long)gm * ldOut + gc)       = make_float2(cc[0], cc[1]);
                *(float2*)((float*)outp + (long)(gm + 8) * ldOut + gc) = make_float2(cc[2], cc[3]);
            } else if (EPI == 3) {
                const long kBase = (long)z * ((long)gridDim.x * 128);
                #pragma unroll
                for (int h = 0; h < 2; ++h)
                    #pragma unroll
                    for (int q = 0; q < 2; ++q) {
                        int gmm = gm + h * 8, gcc = gc + q;
                        float v = cc[h * 2 + q] + biasp[gcc];
                        ((__half*)outp)[(long)gcc * segK + kBase + gmm] = __float2half(v);
                    }
            } else {
                #pragma unroll
                for (int h = 0; h < 2; ++h)
                    #pragma unroll
                    for (int q = 0; q < 2; ++q) {
                        int gmm = gm + h * 8, gcc = gc + q;
                        float v = cc[h * 2 + q];
                        if (EPI == 2) v = (gcc < outN) ? fmaxf(v + biasp[gcc], 0.0f) : 0.0f;
                        __half hi, lo; split_f16(v, hi, lo);
                        __half* o = (__half*)outp + (long)z * outBatch
                                  + (long)gmm * (2L * segK) + gcc;
                        o[0] = hi; o[segK] = lo;
                    }
            }
        }
    }
}

// ---------------------------------------------------------------------------
// elementwise convert: fp32 [R,C] -> fp16 [R, 2C]  (hi | lo)
// ---------------------------------------------------------------------------
__global__ __launch_bounds__(256) void convert_A_ext(const float* __restrict__ in,
                                                     __half* __restrict__ out,
                                                     int R, int C)
{
    long total = (long)R * C;
    for (long idx = blockIdx.x * 256L + threadIdx.x; idx < total; idx += (long)gridDim.x * 256) {
        int r = (int)(idx / C), c = (int)(idx % C);
        __half hi, lo; split_f16(in[idx], hi, lo);
        __half* o = out + (long)r * (2L * C) + c;
        o[0] = hi; o[C] = lo;
    }
}

// ---------------------------------------------------------------------------
// transpose+convert: fp32 in[R,Cc] -> fp16 out, out[c][k] = in[k][c] (k<R else 0)
// BL=true  -> B operand, hi only, row length segK
// BL=false -> A operand, [hi|lo], row length 2*segK
// ---------------------------------------------------------------------------
template<bool BL>
__global__ __launch_bounds__(256) void transpose_ext(const float* __restrict__ in,
                                                     __half* __restrict__ out,
                                                     int R, int Cc, int segK,
                                                     long inBatch, long outBatch)
{
    __shared__ float t[32][33];
    const int z = blockIdx.z;
    in  += (long)z * inBatch;
    out += (long)z * outBatch;
    const int c0 = blockIdx.x * 32, k0 = blockIdx.y * 32;
    const int tx = threadIdx.x, ty = threadIdx.y;   // 32 x 8

    #pragma unroll
    for (int i = 0; i < 4; ++i) {
        int k = k0 + ty + i * 8, c = c0 + tx;
        float v = 0.0f;
        if (k < R && c < Cc) v = in[(long)k * Cc + c];
        t[ty + i * 8][tx] = v;
    }
    __syncthreads();
    #pragma unroll
    for (int i = 0; i < 4; ++i) {
        int c = c0 + ty + i * 8, k = k0 + tx;
        if (c < Cc && k < segK) {
            float v = t[tx][ty + i * 8];
            if (BL) {
                out[(long)c * segK + k] = __float2half(v);
            } else {
                __half hi, lo; split_f16(v, hi, lo);
                __half* o = out + (long)c * (2L * segK) + k;
                o[0] = hi; o[segK] = lo;
            }
        }
    }
}

// ---------------------------------------------------------------------------
// softmax: per token m. Cext [m, 2*NP] (hi|lo), D fp32 [m, NP]
// ---------------------------------------------------------------------------
__global__ __launch_bounds__(256) void softmax_kernel(const float* __restrict__ logits,
                                                      __half* __restrict__ Cext,
                                                      float* __restrict__ D)
{
    extern __shared__ float row[];               // 16384 floats
    __shared__ float red[256];
    const int m = blockIdx.x, tid = threadIdx.x;
    const float* lrow = logits + (size_t)m * NP;

    float mx = -INFINITY;
    for (int i = tid; i < NP; i += 256) { float v = lrow[i]; row[i] = v; mx = fmaxf(mx, v); }
    red[tid] = mx; __syncthreads();
    for (int s = 128; s > 0; s >>= 1) { if (tid < s) red[tid] = fmaxf(red[tid], red[tid + s]); __syncthreads(); }
    mx = red[0]; __syncthreads();

    float sum = 0.0f;
    for (int i = tid; i < NP; i += 256) sum += expf(row[i] - mx);
    red[tid] = sum; __syncthreads();
    for (int s = 128; s > 0; s >>= 1) { if (tid < s) red[tid] += red[tid + s]; __syncthreads(); }
    const float inv = 1.0f / red[0];

    __half* crow = Cext + (size_t)m * (2 * NP);
    for (int i = tid; i < NP; i += 256) {
        float c = expf(row[i] - mx) * inv;
        __half hi, lo; split_f16(c, hi, lo);
        crow[i] = hi; crow[NP + i] = lo;
    }

    float* drow = D + (size_t)m * NP;
    for (int p = tid; p < P_SLOT; p += 256) {
        float l[N_EXP], mn = -INFINITY;
        #pragma unroll
        for (int n = 0; n < N_EXP; n++) { l[n] = row[n * P_SLOT + p]; mn = fmaxf(mn, l[n]); }
        float s2 = 0.0f;
        #pragma unroll
        for (int n = 0; n < N_EXP; n++) { l[n] = expf(l[n] - mn); s2 += l[n]; }
        const float inv2 = 1.0f / s2;
        #pragma unroll
        for (int n = 0; n < N_EXP; n++) drow[n * P_SLOT + p] = l[n] * inv2;
    }
}

// ---------------------------------------------------------------------------
extern "C" void kernel_launch(void* const* d_in, const int* in_sizes, int n_in,
                              void* d_out, int out_size)
{
    const float* x   = (const float*)d_in[0];
    const float* phi = (const float*)d_in[1];
    const float* W1  = (const float*)d_in[2];
    const float* b1  = (const float*)d_in[3];
    const float* W2  = (const float*)d_in[4];
    const float* b2  = (const float*)d_in[5];
    float* out = (float*)d_out;

    float *logits, *D;
    __half *Cext, *Dtext, *xext, *xT, *phiT, *W1T, *W2T, *Xsext, *Hext, *YsT;
    cudaGetSymbolAddress((void**)&logits, g_logits);
    cudaGetSymbolAddress((void**)&D,      g_D);
    cudaGetSymbolAddress((void**)&Cext,   g_Cext);
    cudaGetSymbolAddress((void**)&Dtext,  g_Dtext);
    cudaGetSymbolAddress((void**)&xext,   g_xext);
    cudaGetSymbolAddress((void**)&xT,     g_xT);
    cudaGetSymbolAddress((void**)&phiT,   g_phiT);
    cudaGetSymbolAddress((void**)&W1T,    g_W1T);
    cudaGetSymbolAddress((void**)&W2T,    g_W2T);
    cudaGetSymbolAddress((void**)&Xsext,  g_Xsext);
    cudaGetSymbolAddress((void**)&Hext,   g_Hext);
    cudaGetSymbolAddress((void**)&YsT,    g_YsT);

    cudaFuncSetAttribute(gemm_mma<0,false>, cudaFuncAttributeMaxDynamicSharedMemorySize, SMEM_GEMM);
    cudaFuncSetAttribute(gemm_mma<1,false>, cudaFuncAttributeMaxDynamicSharedMemorySize, SMEM_GEMM);
    cudaFuncSetAttribute(gemm_mma<2,true>,  cudaFuncAttributeMaxDynamicSharedMemorySize, SMEM_GEMM);
    cudaFuncSetAttribute(gemm_mma<3,false>, cudaFuncAttributeMaxDynamicSharedMemorySize, SMEM_GEMM);
    cudaFuncSetAttribute(softmax_kernel,    cudaFuncAttributeMaxDynamicSharedMemorySize, NP * 4);

    dim3 t128(128), t256(256), t32x8(32, 8);

    // operand prep
    convert_A_ext<<<4096, t256>>>(x, xext, M_TOK, D_IN);
    transpose_ext<true><<<dim3(NP/32, D_IN/32, 1),    t32x8>>>(phi, phiT, D_IN, NP, D_IN, 0, 0);
    transpose_ext<true><<<dim3(D_IN/32, M_TOK/32, 1), t32x8>>>(x, xT, M_TOK, D_IN, M_TOK, 0, 0);
    transpose_ext<true><<<dim3(43, D_IN/32, N_EXP),   t32x8>>>(W1, W1T, D_IN, H_HID, D_IN,
                                                      (long)D_IN*H_HID, (long)H_HID*D_IN);
    transpose_ext<true><<<dim3(P_SLOT/32, 44, N_EXP), t32x8>>>(W2, W2T, H_HID, P_SLOT, H_PAD,
                                                      (long)H_HID*P_SLOT, (long)P_SLOT*H_PAD);

    // 1) logits = x @ phi   (M=4096, N=16384, K=1024)
    gemm_mma<0,false><<<dim3(M_TOK/128, NP/128), t128, SMEM_GEMM>>>(
        xext, phiT, nullptr, logits, D_IN, NP, 2*D_IN, D_IN, 0,0,0,0, NP, 0, 0);

    // 2) softmaxes
    softmax_kernel<<<M_TOK, t256, NP*4>>>(logits, Cext, D);

    // 3) D -> Dtext ([hi|lo], transposed)
    transpose_ext<false><<<dim3(NP/32, M_TOK/32, 1), t32x8>>>(D, Dtext, M_TOK, NP, M_TOK, 0, 0);

    // 4) Xs = Dt @ x^T   (M=16384, N=1024, K=4096) -> [hi|lo] segK=1024
    gemm_mma<1,false><<<dim3(NP/128, D_IN/128), t128, SMEM_GEMM>>>(
        Dtext, xT, nullptr, Xsext, M_TOK, D_IN, 2*M_TOK, M_TOK, 0,0,0,0, 0, D_IN, 0);

    // 5) H = relu(Xs @ W1 + b1)  per expert (M=1024, N=1365->1408, K=1024) -> [hi|lo] segK=1408
    gemm_mma<2,true><<<dim3(P_SLOT/128, 11, N_EXP), t128, SMEM_GEMM>>>(
        Xsext, W1T, b1, Hext, D_IN, H_HID, 2*D_IN, D_IN,
        (long)P_SLOT*2*D_IN, (long)H_HID*D_IN, H_HID, (long)P_SLOT*2*H_PAD, 0, H_PAD, H_HID);

    // 6) Ys = H @ W2 + b2  per expert (M=1024, N=1024, K=1408) -> hi-only transposed, row len NP
    gemm_mma<3,false><<<dim3(P_SLOT/128, P_SLOT/128, N_EXP), t128, SMEM_GEMM>>>(
        Hext, W2T, b2, YsT, H_PAD, P_SLOT, 2*H_PAD, H_PAD,
        (long)P_SLOT*2*H_PAD, (long)P_SLOT*H_PAD, P_SLOT, 0, 0, NP, 0);

    // 7) Y = C @ Ys^T  (M=4096, N=1024, K=16384)
    gemm_mma<0,false><<<dim3(M_TOK/128, D_IN/128), t128, SMEM_GEMM>>>(
        Cext, YsT, nullptr, out, NP, D_IN, 2*NP, NP, 0,0,0,0, D_IN, 0, 0);

    (void)in_sizes; (void)n_in; (void)out_size;
}

// round 6
// speedup vs baseline: 11.8775x; 1.6485x over previous
#include <cuda_runtime.h>
#include <cuda_fp16.h>
#include <math.h>
#include <stdint.h>

// ---------------- problem dims ----------------
#define M_TOK 4096
#define D_IN  1024
#define N_EXP 16
#define P_SLOT 1024
#define H_HID 1365
#define H_PAD 1408
#define NP    16384

// ---------------- scratch (all GEMM operands plain fp16, K-major) ----------------
__device__ float  g_logits[(size_t)M_TOK*NP];       // 268 MB fp32
__device__ __half g_Ch [(size_t)M_TOK*NP];          // combine weights [m, np]
__device__ __half g_Dh [(size_t)M_TOK*NP];          // dispatch weights [m, np]
__device__ __half g_Dt [(size_t)NP*M_TOK];          // dispatch transposed [np, m]
__device__ __half g_xf [(size_t)M_TOK*D_IN];        // x fp16 [m, d]
__device__ __half g_xT [(size_t)D_IN*M_TOK];        // x transposed [d, m]
__device__ __half g_phiT[(size_t)NP*D_IN];          // phi transposed [np, d]
__device__ __half g_W1T [(size_t)N_EXP*H_HID*D_IN]; // [n][h, d]
__device__ __half g_W2T [(size_t)N_EXP*P_SLOT*H_PAD]; // [n][o, h_pad]
__device__ __half g_Xs  [(size_t)NP*D_IN];          // slot inputs [np, d]
__device__ __half g_H   [(size_t)N_EXP*P_SLOT*H_PAD]; // hidden [n][p, h_pad] (padded cols zero)
__device__ __half g_YsT [(size_t)P_SLOT*NP];        // slot outputs transposed [o, np]

// ---------------- helpers ----------------
__device__ __forceinline__ uint32_t smem_u32(const void* p) {
    return (uint32_t)__cvta_generic_to_shared(p);
}
#define SWZ(x) ((x) ^ (((x) >> 3) & 0x70))

__device__ __forceinline__ void ldsm_x4(uint32_t* r, uint32_t addr) {
    asm volatile("ldmatrix.sync.aligned.m8n8.x4.shared.b16 {%0,%1,%2,%3}, [%4];"
                 : "=r"(r[0]), "=r"(r[1]), "=r"(r[2]), "=r"(r[3]) : "r"(addr));
}
__device__ __forceinline__ void mma16816(float* c, const uint32_t* a, const uint32_t* b) {
    asm volatile("mma.sync.aligned.m16n8k16.row.col.f32.f16.f16.f32 "
        "{%0,%1,%2,%3}, {%4,%5,%6,%7}, {%8,%9}, {%0,%1,%2,%3};"
        : "+f"(c[0]), "+f"(c[1]), "+f"(c[2]), "+f"(c[3])
        : "r"(a[0]), "r"(a[1]), "r"(a[2]), "r"(a[3]), "r"(b[0]), "r"(b[1]));
}
__device__ __forceinline__ void cp16(uint32_t dst, const void* src, int srcsize) {
    asm volatile("cp.async.cg.shared.global [%0], [%1], 16, %2;"
                 :: "r"(dst), "l"(src), "r"(srcsize) : "memory");
}
#define CP_COMMIT() asm volatile("cp.async.commit_group;" ::: "memory")
#define CP_WAIT(n)  asm volatile("cp.async.wait_group %0;" :: "n"(n) : "memory")

// smem: 2 stages x (A 16KB + B 16KB)
#define STG_BYTES  32768
#define SMEM_GEMM  (2 * STG_BYTES)

// ---------------------------------------------------------------------------
// fp16 HMMA GEMM: D[128,128] = A[M,K] * B[N,K]^T (both K-major fp16)
// CTA 128x128, 4 warps each 64x64, 2-stage cp.async pipeline.
// EPI: 0 = fp32 row-major (ldOut)
//      1 = fp16 row-major (ldOut16 = segK)
//      2 = fp16 row-major + bias + relu + zero-pad cols [outN, segK)
//      3 = fp16 TRANSPOSED (row = gc, k = z*gridX*128 + gm) + bias; row length segK
// ---------------------------------------------------------------------------
template<int EPI, bool BCHECK>
__global__ __launch_bounds__(128, 2)
void gemm_f16(const __half* __restrict__ A, const __half* __restrict__ B,
              const float* __restrict__ bias, void* __restrict__ outp,
              int K, int Nrows, int ldA, int ldB,
              long sA, long sB, long sBias, long outBatch,
              int ldOut, int segK, int outN)
{
    extern __shared__ char smraw[];
    const uint32_t smb = smem_u32(smraw);
    const int tid = threadIdx.x, wid = tid >> 5, lane = tid & 31;
    const int z  = blockIdx.z;
    const int m0 = blockIdx.x * 128, n0 = blockIdx.y * 128;
    A += (long)z * sA;
    B += (long)z * sB;
    const float* biasp = bias ? (bias + (long)z * sBias) : bias;

    const int nCh = K >> 6;           // K chunks of 64 fp16 (128B)
    const int lrow = tid >> 3;        // 0..15
    const int lj   = tid & 7;         // 16B lane within 128B row

    auto issue = [&](int c) {
        const uint32_t smA = smb + (c & 1) * STG_BYTES;
        const uint32_t smB = smA + 16384;
        const long kb = (long)c * 64 + lj * 8;   // fp16 element offset
        #pragma unroll
        for (int i = 0; i < 8; ++i) {
            int r = lrow + i * 16;
            cp16(smA + SWZ(r * 128 + lj * 16), A + (long)(m0 + r) * ldA + kb, 16);
        }
        #pragma unroll
        for (int i = 0; i < 8; ++i) {
            int r = lrow + i * 16;
            int ok = (!BCHECK) || (n0 + r) < Nrows;
            const __half* src = B + (long)(ok ? (n0 + r) : 0) * ldB + kb;
            cp16(smB + SWZ(r * 128 + lj * 16), src, ok ? 16 : 0);
        }
        CP_COMMIT();
    };

    float acc[4][8][4] = {};                 // [mb][nb][c0..c3]
    const int wm = (wid >> 1) * 64;          // warp m offset (0/64)
    const int wn = (wid & 1) * 64;           // warp n offset (0/64)

    issue(0);

    for (int c = 0; c < nCh; ++c) {
        if (c + 1 < nCh) { issue(c + 1); CP_WAIT(1); } else { CP_WAIT(0); }
        __syncthreads();

        const uint32_t smA = smb + (c & 1) * STG_BYTES;
        const uint32_t smB = smA + 16384;

        #pragma unroll
        for (int ks = 0; ks < 4; ++ks) {
            const int kb = ks * 32;          // byte offset of k16 within 128B row
            uint32_t af[4][4], bf[8][2];
            #pragma unroll
            for (int mb = 0; mb < 4; ++mb) {
                int row = wm + mb * 16 + (lane & 15);
                ldsm_x4(af[mb], smA + SWZ(row * 128 + kb + ((lane >> 4) << 4)));
            }
            #pragma unroll
            for (int npair = 0; npair < 4; ++npair) {
                int row = wn + npair * 16 + (lane & 7) + ((lane >> 4) << 3);
                uint32_t r4[4];
                ldsm_x4(r4, smB + SWZ(row * 128 + kb + (((lane >> 3) & 1) << 4)));
                bf[npair*2  ][0] = r4[0]; bf[npair*2  ][1] = r4[1];
                bf[npair*2+1][0] = r4[2]; bf[npair*2+1][1] = r4[3];
            }
            #pragma unroll
            for (int mb = 0; mb < 4; ++mb)
                #pragma unroll
                for (int nb = 0; nb < 8; ++nb)
                    mma16816(acc[mb][nb], af[mb], bf[nb]);
        }
        __syncthreads();
    }

    // ---------------- epilogue ----------------
    const int erow = lane >> 2;
    const int ecol = (lane & 3) * 2;
    #pragma unroll
    for (int mb = 0; mb < 4; ++mb) {
        #pragma unroll
        for (int nb = 0; nb < 8; ++nb) {
            float* cc = acc[mb][nb];
            const int gm = m0 + wm + mb * 16 + erow;
            const int gc = n0 + wn + nb * 8 + ecol;
            if (EPI == 0) {
                *(float2*)((float*)outp + (long)gm * ldOut + gc)       = make_float2(cc[0], cc[1]);
                *(float2*)((float*)outp + (long)(gm + 8) * ldOut + gc) = make_float2(cc[2], cc[3]);
            } else if (EPI == 3) {
                const long kBase = (long)z * ((long)gridDim.x * 128);
                #pragma unroll
                for (int h = 0; h < 2; ++h)
                    #pragma unroll
                    for (int q = 0; q < 2; ++q) {
                        int gmm = gm + h * 8, gcc = gc + q;
                        float v = cc[h * 2 + q] + biasp[gcc];
                        ((__half*)outp)[(long)gcc * segK + kBase + gmm] = __float2half(v);
                    }
            } else {
                __half* ob = (__half*)outp + (long)z * outBatch;
                #pragma unroll
                for (int h = 0; h < 2; ++h) {
                    int gmm = gm + h * 8;
                    float v0 = cc[h * 2], v1 = cc[h * 2 + 1];
                    if (EPI == 2) {
                        v0 = (gc     < outN) ? fmaxf(v0 + biasp[gc],     0.0f) : 0.0f;
                        v1 = (gc + 1 < outN) ? fmaxf(v1 + biasp[gc + 1], 0.0f) : 0.0f;
                    }
                    __half2 hv = __floats2half2_rn(v0, v1);
                    *(__half2*)(ob + (long)gmm * segK + gc) = hv;
                }
            }
        }
    }
}

// ---------------------------------------------------------------------------
// elementwise convert fp32 -> fp16
// ---------------------------------------------------------------------------
__global__ __launch_bounds__(256) void convert_f16(const float* __restrict__ in,
                                                   __half* __restrict__ out, long total)
{
    for (long idx = blockIdx.x * 256L + threadIdx.x; idx < total; idx += (long)gridDim.x * 256)
        out[idx] = __float2half(in[idx]);
}

// ---------------------------------------------------------------------------
// transpose+convert: fp32 in[R,Cc] -> fp16 out[Cc, segK], out[c][k]=in[k][c] (k<R else 0)
// ---------------------------------------------------------------------------
__global__ __launch_bounds__(256) void transpose_f32(const float* __restrict__ in,
                                                     __half* __restrict__ out,
                                                     int R, int Cc, int segK,
                                                     long inBatch, long outBatch)
{
    __shared__ float t[32][33];
    const int z = blockIdx.z;
    in  += (long)z * inBatch;
    out += (long)z * outBatch;
    const int c0 = blockIdx.x * 32, k0 = blockIdx.y * 32;
    const int tx = threadIdx.x, ty = threadIdx.y;   // 32 x 8

    #pragma unroll
    for (int i = 0; i < 4; ++i) {
        int k = k0 + ty + i * 8, c = c0 + tx;
        float v = 0.0f;
        if (k < R && c < Cc) v = in[(long)k * Cc + c];
        t[ty + i * 8][tx] = v;
    }
    __syncthreads();
    #pragma unroll
    for (int i = 0; i < 4; ++i) {
        int c = c0 + ty + i * 8, k = k0 + tx;
        if (c < Cc && k < segK)
            out[(long)c * segK + k] = __float2half(t[tx][ty + i * 8]);
    }
}

// ---------------------------------------------------------------------------
// fp16 transpose: in[R,Cc] -> out[Cc, R]
// ---------------------------------------------------------------------------
__global__ __launch_bounds__(256) void transpose_f16(const __half* __restrict__ in,
                                                     __half* __restrict__ out,
                                                     int R, int Cc)
{
    __shared__ __half t[32][40];
    const int c0 = blockIdx.x * 32, k0 = blockIdx.y * 32;
    const int tx = threadIdx.x, ty = threadIdx.y;   // 32 x 8

    #pragma unroll
    for (int i = 0; i < 4; ++i)
        t[ty + i * 8][tx] = in[(long)(k0 + ty + i * 8) * Cc + c0 + tx];
    __syncthreads();
    #pragma unroll
    for (int i = 0; i < 4; ++i)
        out[(long)(c0 + ty + i * 8) * R + k0 + tx] = t[tx][ty + i * 8];
}

// ---------------------------------------------------------------------------
// softmax: per token m. Ch [m, NP] fp16, Dh [m, NP] fp16 (both row-major)
// ---------------------------------------------------------------------------
__global__ __launch_bounds__(256) void softmax_kernel(const float* __restrict__ logits,
                                                      __half* __restrict__ Ch,
                                                      __half* __restrict__ Dh)
{
    extern __shared__ float row[];               // 16384 floats
    __shared__ float red[256];
    const int m = blockIdx.x, tid = threadIdx.x;
    const float* lrow = logits + (size_t)m * NP;

    float mx = -INFINITY;
    for (int i = tid; i < NP; i += 256) { float v = lrow[i]; row[i] = v; mx = fmaxf(mx, v); }
    red[tid] = mx; __syncthreads();
    for (int s = 128; s > 0; s >>= 1) { if (tid < s) red[tid] = fmaxf(red[tid], red[tid + s]); __syncthreads(); }
    mx = red[0]; __syncthreads();

    float sum = 0.0f;
    for (int i = tid; i < NP; i += 256) sum += expf(row[i] - mx);
    red[tid] = sum; __syncthreads();
    for (int s = 128; s > 0; s >>= 1) { if (tid < s) red[tid] += red[tid + s]; __syncthreads(); }
    const float inv = 1.0f / red[0];

    __half* crow = Ch + (size_t)m * NP;
    for (int i = tid; i < NP; i += 256)
        crow[i] = __float2half(expf(row[i] - mx) * inv);

    __half* drow = Dh + (size_t)m * NP;
    for (int p = tid; p < P_SLOT; p += 256) {
        float l[N_EXP], mn = -INFINITY;
        #pragma unroll
        for (int n = 0; n < N_EXP; n++) { l[n] = row[n * P_SLOT + p]; mn = fmaxf(mn, l[n]); }
        float s2 = 0.0f;
        #pragma unroll
        for (int n = 0; n < N_EXP; n++) { l[n] = expf(l[n] - mn); s2 += l[n]; }
        const float inv2 = 1.0f / s2;
        #pragma unroll
        for (int n = 0; n < N_EXP; n++) drow[n * P_SLOT + p] = __float2half(l[n] * inv2);
    }
}

// ---------------------------------------------------------------------------
extern "C" void kernel_launch(void* const* d_in, const int* in_sizes, int n_in,
                              void* d_out, int out_size)
{
    const float* x   = (const float*)d_in[0];
    const float* phi = (const float*)d_in[1];
    const float* W1  = (const float*)d_in[2];
    const float* b1  = (const float*)d_in[3];
    const float* W2  = (const float*)d_in[4];
    const float* b2  = (const float*)d_in[5];
    float* out = (float*)d_out;

    float* logits;
    __half *Ch, *Dh, *Dt, *xf, *xT, *phiT, *W1T, *W2T, *Xs, *H, *YsT;
    cudaGetSymbolAddress((void**)&logits, g_logits);
    cudaGetSymbolAddress((void**)&Ch,   g_Ch);
    cudaGetSymbolAddress((void**)&Dh,   g_Dh);
    cudaGetSymbolAddress((void**)&Dt,   g_Dt);
    cudaGetSymbolAddress((void**)&xf,   g_xf);
    cudaGetSymbolAddress((void**)&xT,   g_xT);
    cudaGetSymbolAddress((void**)&phiT, g_phiT);
    cudaGetSymbolAddress((void**)&W1T,  g_W1T);
    cudaGetSymbolAddress((void**)&W2T,  g_W2T);
    cudaGetSymbolAddress((void**)&Xs,   g_Xs);
    cudaGetSymbolAddress((void**)&H,    g_H);
    cudaGetSymbolAddress((void**)&YsT,  g_YsT);

    cudaFuncSetAttribute(gemm_f16<0,false>, cudaFuncAttributeMaxDynamicSharedMemorySize, SMEM_GEMM);
    cudaFuncSetAttribute(gemm_f16<1,false>, cudaFuncAttributeMaxDynamicSharedMemorySize, SMEM_GEMM);
    cudaFuncSetAttribute(gemm_f16<2,true>,  cudaFuncAttributeMaxDynamicSharedMemorySize, SMEM_GEMM);
    cudaFuncSetAttribute(gemm_f16<3,false>, cudaFuncAttributeMaxDynamicSharedMemorySize, SMEM_GEMM);
    cudaFuncSetAttribute(softmax_kernel,    cudaFuncAttributeMaxDynamicSharedMemorySize, NP * 4);

    dim3 t128(128), t256(256), t32x8(32, 8);

    // operand prep
    convert_f16<<<2048, t256>>>(x, xf, (long)M_TOK * D_IN);
    transpose_f32<<<dim3(NP/32, D_IN/32, 1),    t32x8>>>(phi, phiT, D_IN, NP, D_IN, 0, 0);
    transpose_f32<<<dim3(D_IN/32, M_TOK/32, 1), t32x8>>>(x, xT, M_TOK, D_IN, M_TOK, 0, 0);
    transpose_f32<<<dim3(43, D_IN/32, N_EXP),   t32x8>>>(W1, W1T, D_IN, H_HID, D_IN,
                                                 (long)D_IN*H_HID, (long)H_HID*D_IN);
    transpose_f32<<<dim3(P_SLOT/32, 44, N_EXP), t32x8>>>(W2, W2T, H_HID, P_SLOT, H_PAD,
                                                 (long)H_HID*P_SLOT, (long)P_SLOT*H_PAD);

    // 1) logits = x @ phi   (M=4096, N=16384, K=1024)
    gemm_f16<0,false><<<dim3(M_TOK/128, NP/128), t128, SMEM_GEMM>>>(
        xf, phiT, nullptr, logits, D_IN, NP, D_IN, D_IN, 0,0,0,0, NP, 0, 0);

    // 2) softmaxes -> Ch [m,np], Dh [m,np]
    softmax_kernel<<<M_TOK, t256, NP*4>>>(logits, Ch, Dh);

    // 3) Dh -> Dt (fp16 transpose)
    transpose_f16<<<dim3(NP/32, M_TOK/32), t32x8>>>(Dh, Dt, M_TOK, NP);

    // 4) Xs = Dt @ x^T   (M=16384, N=1024, K=4096) -> fp16 rows, segK=D_IN
    gemm_f16<1,false><<<dim3(NP/128, D_IN/128), t128, SMEM_GEMM>>>(
        Dt, xT, nullptr, Xs, M_TOK, D_IN, M_TOK, M_TOK, 0,0,0,0, 0, D_IN, 0);

    // 5) H = relu(Xs @ W1 + b1)  per expert (M=1024, N=1365->1408, K=1024) -> fp16, segK=H_PAD
    gemm_f16<2,true><<<dim3(P_SLOT/128, 11, N_EXP), t128, SMEM_GEMM>>>(
        Xs, W1T, b1, H, D_IN, H_HID, D_IN, D_IN,
        (long)P_SLOT*D_IN, (long)H_HID*D_IN, H_HID, (long)P_SLOT*H_PAD, 0, H_PAD, H_HID);

    // 6) Ys = H @ W2 + b2  per expert (M=1024, N=1024, K=1408) -> fp16 transposed, row len NP
    gemm_f16<3,false><<<dim3(P_SLOT/128, P_SLOT/128, N_EXP), t128, SMEM_GEMM>>>(
        H, W2T, b2, YsT, H_PAD, P_SLOT, H_PAD, H_PAD,
        (long)P_SLOT*H_PAD, (long)P_SLOT*H_PAD, P_SLOT, 0, 0, NP, 0);

    // 7) Y = C @ Ys^T  (M=4096, N=1024, K=16384) -> fp32
    gemm_f16<0,false><<<dim3(M_TOK/128, D_IN/128), t128, SMEM_GEMM>>>(
        Ch, YsT, nullptr, out, NP, D_IN, NP, NP, 0,0,0,0, D_IN, 0, 0);

    (void)in_sizes; (void)n_in; (void)out_size;
}